// round 15
// baseline (speedup 1.0000x reference)
#include <cuda_runtime.h>
#include <cuda_bf16.h>
#include <cstdint>

#define NG 128
#define NPER0 512
#define N0TOT 65536
#define E_TOT 1048576
#define EPG 8192
#define INC 100
#define HIDC 128
#define K1C 410
#define K2C 328
#define K3C 263
#define N1TOT (NG*K1C)
#define N2TOT (NG*K2C)
#define BN_EPS 1e-5f

#define LDB 136            // bf16 units per smem row (pad: conflict-free fragments)
#define TILE_ELEMS (128*LDB)
#define MM_SMEM (4*TILE_ELEMS*2)   // 4 bf16 tiles = 139264 B

// ---------------- device scratch ----------------
__device__ __align__(16) float d_bufA[N0TOT*HIDC];
__device__ __align__(16) float d_bufB[N0TOT*HIDC];
__device__ int   d_indeg[NG*NPER0];
__device__ int   d_coff[NG*NPER0];
__device__ float d_dinv[NG*NPER0];
__device__ int   d_srcE[E_TOT];
__device__ int   d_dstE[E_TOT];
__device__ unsigned char d_em[E_TOT];
__device__ long long d_csr[E_TOT];
__device__ __align__(16) float d_bnsum3[3][HIDC];
__device__ __align__(16) float d_bnsq3[3][HIDC];
__device__ float d_attinv3[3];
__device__ __align__(16) float d_read[3*NG*2*HIDC];
__device__ int   d_klocal[NG*NPER0];
__device__ float d_ksc[NG*NPER0];
__device__ __align__(16) float d_bnA[3][HIDC];
__device__ __align__(16) float d_bnB[3][HIDC];

// ---------------- mma.sync bf16 helper (sm_80+, valid on sm_103) ----------------
__device__ __forceinline__ void mma_bf16(float* d, const uint32_t* a, const uint32_t* b) {
    asm volatile(
        "mma.sync.aligned.m16n8k16.row.col.f32.bf16.bf16.f32 "
        "{%0,%1,%2,%3},{%4,%5,%6,%7},{%8,%9},{%0,%1,%2,%3};"
        : "+f"(d[0]), "+f"(d[1]), "+f"(d[2]), "+f"(d[3])
        : "r"(a[0]), "r"(a[1]), "r"(a[2]), "r"(a[3]), "r"(b[0]), "r"(b[1]));
}
__device__ __forceinline__ uint32_t pack_hi(float x, float y) {
    __nv_bfloat162 p = __floats2bfloat162_rn(x, y);
    return *(uint32_t*)&p;
}

// frag compute core: acc[16][4] over warp tile 64x32, K-steps [0, nk16)
__device__ __forceinline__ void mm_core(const __nv_bfloat16* Ah, const __nv_bfloat16* Al,
                                        const __nv_bfloat16* Bh, const __nv_bfloat16* Bl,
                                        int mw, int nw, int g, int tg, int nk16,
                                        float acc[16][4]) {
#pragma unroll
    for (int pass = 0; pass < 3; pass++) {
        const __nv_bfloat16* As = (pass == 2) ? Al : Ah;
        const __nv_bfloat16* Bs = (pass == 1) ? Bl : Bh;
        for (int ks = 0; ks < nk16; ks++) {
            const int kb = ks * 16 + tg * 2;
            uint32_t a[4][4], b[4][2];
#pragma unroll
            for (int mt = 0; mt < 4; mt++) {
                int r = mw + mt * 16 + g;
                a[mt][0] = *(const uint32_t*)&As[r * LDB + kb];
                a[mt][1] = *(const uint32_t*)&As[(r + 8) * LDB + kb];
                a[mt][2] = *(const uint32_t*)&As[r * LDB + kb + 8];
                a[mt][3] = *(const uint32_t*)&As[(r + 8) * LDB + kb + 8];
            }
#pragma unroll
            for (int nt = 0; nt < 4; nt++) {
                int n = nw + nt * 8 + g;
                b[nt][0] = *(const uint32_t*)&Bs[n * LDB + kb];
                b[nt][1] = *(const uint32_t*)&Bs[n * LDB + kb + 8];
            }
#pragma unroll
            for (int mt = 0; mt < 4; mt++)
#pragma unroll
                for (int nt = 0; nt < 4; nt++) mma_bf16(acc[mt * 4 + nt], a[mt], b[nt]);
        }
    }
}

// ====== gathered GEMM (levels 1,2): A row j = relu(X[klocal]*bnA+bnB)*ksc ======
__global__ __launch_bounds__(256) void k_mmg(const float* __restrict__ X,
                                             const float* __restrict__ W,
                                             float* __restrict__ C,
                                             int kcur, int nprev, int lvl) {
    extern __shared__ char sm[];
    __nv_bfloat16* Ah = (__nv_bfloat16*)sm;
    __nv_bfloat16* Al = Ah + TILE_ELEMS;
    __nv_bfloat16* Bh = Al + TILE_ELEMS;
    __nv_bfloat16* Bl = Bh + TILE_ELEMS;
    __shared__ float sA[128], sB[128], sk[128];
    __shared__ int ssrc[128];
    const int t = threadIdx.x, w = t >> 5, lane = t & 31, g = lane >> 2, tg = lane & 3;
    const long long row0 = (long long)blockIdx.x * 128;

    if (t < 128) {
        sA[t] = d_bnA[lvl][t];
        sB[t] = d_bnB[lvl][t];
        int rr = (int)row0 + t;
        int gg = rr / kcur, j = rr - gg * kcur;
        ssrc[t] = gg * nprev + d_klocal[(gg << 9) + j];
        sk[t] = d_ksc[(gg << 9) + j];
    }
    __syncthreads();

    for (int i = t; i < 128 * 64; i += 256) {
        int r = i >> 6, k2 = (i & 63) * 2;
        float2 v = *(const float2*)&X[(long long)ssrc[r] * 128 + k2];
        float kk = sk[r];
        float v0 = fmaxf(fmaf(v.x, sA[k2], sB[k2]), 0.f) * kk;
        float v1 = fmaxf(fmaf(v.y, sA[k2 + 1], sB[k2 + 1]), 0.f) * kk;
        __nv_bfloat16 h0 = __float2bfloat16(v0), h1 = __float2bfloat16(v1);
        *(uint32_t*)&Ah[r * LDB + k2] = pack_hi(v0, v1);
        *(uint32_t*)&Al[r * LDB + k2] =
            pack_hi(v0 - __bfloat162float(h0), v1 - __bfloat162float(h1));
    }
    for (int i = t; i < 128 * 128; i += 256) {
        int k = i >> 7, n = i & 127;
        float v = W[i];
        __nv_bfloat16 h = __float2bfloat16(v);
        Bh[n * LDB + k] = h;
        Bl[n * LDB + k] = __float2bfloat16(v - __bfloat162float(h));
    }
    __syncthreads();

    const int mw = (w & 1) * 64, nw = (w >> 1) * 32;
    float acc[16][4];
#pragma unroll
    for (int i = 0; i < 16; i++)
#pragma unroll
        for (int j = 0; j < 4; j++) acc[i][j] = 0.f;

    mm_core(Ah, Al, Bh, Bl, mw, nw, g, tg, 8, acc);

#pragma unroll
    for (int mt = 0; mt < 4; mt++)
#pragma unroll
        for (int nt = 0; nt < 4; nt++) {
            long long r = row0 + mw + mt * 16 + g;
            int c = nw + nt * 8 + tg * 2;
            float* ap = acc[mt * 4 + nt];
            *(float2*)&C[r * 128 + c] = make_float2(ap[0], ap[1]);
            *(float2*)&C[(r + 8) * 128 + c] = make_float2(ap[2], ap[3]);
        }
}

// ====== fused: h = relu(x@Wp + bp); C = h @ W1  (K phase A padded 100->112) ======
__global__ __launch_bounds__(256) void k_mm2(const float* __restrict__ X,
                                             const float* __restrict__ Wp,
                                             const float* __restrict__ bp,
                                             const float* __restrict__ W1,
                                             float* __restrict__ C) {
    extern __shared__ char sm[];
    __nv_bfloat16* Ah = (__nv_bfloat16*)sm;
    __nv_bfloat16* Al = Ah + TILE_ELEMS;
    __nv_bfloat16* Bh = Al + TILE_ELEMS;
    __nv_bfloat16* Bl = Bh + TILE_ELEMS;
    __shared__ float sbias[128];
    const int t = threadIdx.x, w = t >> 5, lane = t & 31, g = lane >> 2, tg = lane & 3;
    const long long row0 = (long long)blockIdx.x * 128;

    if (t < 128) sbias[t] = bp[t];
    // zero pad region k in [96,112) of all 4 tiles
    for (int i = t; i < 128 * 16; i += 256) {
        int r = i >> 4, k = 96 + (i & 15);
        Ah[r * LDB + k] = __nv_bfloat16(0.f);
        Al[r * LDB + k] = __nv_bfloat16(0.f);
        Bh[r * LDB + k] = __nv_bfloat16(0.f);
        Bl[r * LDB + k] = __nv_bfloat16(0.f);
    }
    __syncthreads();
    for (int i = t; i < 128 * 50; i += 256) {   // x: 128 rows x 100 cols (50 float2)
        int r = i / 50, k2 = (i - r * 50) * 2;
        float2 v = *(const float2*)&X[(row0 + r) * INC + k2];
        __nv_bfloat16 hx = __float2bfloat16(v.x), hy = __float2bfloat16(v.y);
        *(uint32_t*)&Ah[r * LDB + k2] = pack_hi(v.x, v.y);
        *(uint32_t*)&Al[r * LDB + k2] =
            pack_hi(v.x - __bfloat162float(hx), v.y - __bfloat162float(hy));
    }
    for (int i = t; i < INC * 128; i += 256) {
        int k = i >> 7, n = i & 127;
        float v = Wp[i];
        __nv_bfloat16 h = __float2bfloat16(v);
        Bh[n * LDB + k] = h;
        Bl[n * LDB + k] = __float2bfloat16(v - __bfloat162float(h));
    }
    __syncthreads();

    const int mw = (w & 1) * 64, nw = (w >> 1) * 32;
    float acc[16][4];
#pragma unroll
    for (int i = 0; i < 16; i++)
#pragma unroll
        for (int j = 0; j < 4; j++) acc[i][j] = 0.f;

    mm_core(Ah, Al, Bh, Bl, mw, nw, g, tg, 7, acc);   // 112/16 = 7 ksteps
    __syncthreads();   // all smem reads done before overwrite

    // bias+relu, split h -> Ah/Al (k index = output col); then load W1 -> Bh/Bl
#pragma unroll
    for (int mt = 0; mt < 4; mt++)
#pragma unroll
        for (int nt = 0; nt < 4; nt++) {
            int r = mw + mt * 16 + g;
            int c = nw + nt * 8 + tg * 2;
            float* ap = acc[mt * 4 + nt];
            float v0 = fmaxf(ap[0] + sbias[c], 0.f);
            float v1 = fmaxf(ap[1] + sbias[c + 1], 0.f);
            float v2 = fmaxf(ap[2] + sbias[c], 0.f);
            float v3 = fmaxf(ap[3] + sbias[c + 1], 0.f);
            __nv_bfloat16 h0 = __float2bfloat16(v0), h1 = __float2bfloat16(v1);
            __nv_bfloat16 h2 = __float2bfloat16(v2), h3 = __float2bfloat16(v3);
            *(uint32_t*)&Ah[r * LDB + c] = pack_hi(v0, v1);
            *(uint32_t*)&Al[r * LDB + c] =
                pack_hi(v0 - __bfloat162float(h0), v1 - __bfloat162float(h1));
            *(uint32_t*)&Ah[(r + 8) * LDB + c] = pack_hi(v2, v3);
            *(uint32_t*)&Al[(r + 8) * LDB + c] =
                pack_hi(v2 - __bfloat162float(h2), v3 - __bfloat162float(h3));
            ap[0] = ap[1] = ap[2] = ap[3] = 0.f;
        }
    for (int i = t; i < 128 * 128; i += 256) {
        int k = i >> 7, n = i & 127;
        float v = W1[i];
        __nv_bfloat16 h = __float2bfloat16(v);
        Bh[n * LDB + k] = h;
        Bl[n * LDB + k] = __float2bfloat16(v - __bfloat162float(h));
    }
    __syncthreads();

    mm_core(Ah, Al, Bh, Bl, mw, nw, g, tg, 8, acc);

#pragma unroll
    for (int mt = 0; mt < 4; mt++)
#pragma unroll
        for (int nt = 0; nt < 4; nt++) {
            long long r = row0 + mw + mt * 16 + g;
            int c = nw + nt * 8 + tg * 2;
            float* ap = acc[mt * 4 + nt];
            *(float2*)&C[r * 128 + c] = make_float2(ap[0], ap[1]);
            *(float2*)&C[(r + 8) * 128 + c] = make_float2(ap[2], ap[3]);
        }
}

// ================= init: edge load + count + scan + CSR fill (level 0) ===========
__global__ __launch_bounds__(512) void k_init(const int* __restrict__ ei,
                                              const float* __restrict__ at0,
                                              const float* __restrict__ at1,
                                              const float* __restrict__ at2) {
    __shared__ int scnt[512];
    __shared__ int rk[EPG];
    __shared__ float dv[512];
    __shared__ int wtmp[16], wexcl[16];
    const int g = blockIdx.x, t = threadIdx.x, lane = t & 31, wid = t >> 5;
    scnt[t] = 0;
    if (g == 0) {
        if (t < 384) {
            ((float*)d_bnsum3)[t] = 0.f;
            ((float*)d_bnsq3)[t] = 0.f;
        }
        if (wid >= 13) {
            const float* ap = (wid == 13) ? at0 : (wid == 14) ? at1 : at2;
            float s = 0.f;
#pragma unroll
            for (int q = 0; q < 4; q++) { float v = ap[lane + 32 * q]; s += v * v; }
#pragma unroll
            for (int o = 16; o > 0; o >>= 1) s += __shfl_xor_sync(0xffffffffu, s, o);
            if (lane == 0) d_attinv3[wid - 13] = rsqrtf(s);
        }
    }
    __syncthreads();
    const int e0 = g * EPG;
    for (int i = t; i < EPG; i += 512) {
        int sl = ei[e0 + i] - (g << 9);
        int dl = ei[E_TOT + e0 + i] - (g << 9);
        rk[i] = atomicAdd(&scnt[dl], 1);
        d_srcE[e0 + i] = sl;
        d_dstE[e0 + i] = dl;
        d_em[e0 + i] = 1;
    }
    __syncthreads();
    int v = scnt[t];
    int incl = v;
#pragma unroll
    for (int o = 1; o < 32; o <<= 1) {
        int y = __shfl_up_sync(0xffffffffu, incl, o);
        if (lane >= o) incl += y;
    }
    if (lane == 31) wtmp[wid] = incl;
    __syncthreads();
    if (t < 16) {
        int w = wtmp[t], s = w;
#pragma unroll
        for (int o = 1; o < 16; o <<= 1) {
            int y = __shfl_up_sync(0x0000ffffu, s, o);
            if (t >= o) s += y;
        }
        wexcl[t] = s - w;
    }
    __syncthreads();
    int excl = incl - v + wexcl[wid];
    {
        int node = (g << 9) + t;
        d_coff[node] = e0 + excl;
        d_indeg[node] = v;
        float di = rsqrtf((float)v + 1.f);
        d_dinv[node] = di;
        dv[t] = di;
        scnt[t] = excl;
    }
    __syncthreads();
    for (int i = t; i < EPG; i += 512) {
        int sl = d_srcE[e0 + i], dl = d_dstE[e0 + i];
        int slot = scnt[dl] + rk[i];
        union { struct { int s; float c; } p; long long ll; } u;
        u.p.s = sl;
        u.p.c = dv[sl] * dv[dl];
        d_csr[e0 + slot] = u.ll;
    }
}

// ================= conv: quarter-channel smem gather + fused BN stats =====
__global__ __launch_bounds__(512) void k_conv(const float* __restrict__ xl,
                                              float* __restrict__ out,
                                              const float* __restrict__ bias,
                                              int nper, int lvl) {
    extern __shared__ float sf[];
    __shared__ float sred[1024];
    const int g = blockIdx.x, q = blockIdx.y;
    const int t = threadIdx.x, wid = t >> 5, lane = t & 31;
    const long long rb = (long long)g * nper;

    for (int idx = t; idx < nper * 8; idx += 512) {
        int r = idx >> 3, c4 = idx & 7;
        ((float4*)sf)[r * 8 + c4] = ((const float4*)(xl + (rb + r) * 128 + q * 32))[c4];
    }
    __syncthreads();

    const int ch = q * 32 + lane;
    const float bb = bias[ch];
    float bs = 0.f, bq = 0.f;
    for (int node = wid; node < nper; node += 16) {
        int gnode = (g << 9) + node;
        int base = d_coff[gnode];
        int cnt = d_indeg[gnode];
        float a = 0.f;
#pragma unroll 4
        for (int j = 0; j < cnt; j++) {
            long long ll = __ldg(&d_csr[base + j]);
            int sl = (int)(ll & 0xffffffffll);
            float w = __int_as_float((int)(ll >> 32));
            a += w * sf[sl * 32 + lane];
        }
        float di = d_dinv[gnode];
        a += di * di * sf[node * 32 + lane] + bb;
        out[(rb + node) * 128 + ch] = a;
        bs += a;
        bq += a * a;
    }
    sred[wid * 32 + lane] = bs;
    sred[512 + wid * 32 + lane] = bq;
    __syncthreads();
    if (t < 32) {
        float s = 0.f, s2 = 0.f;
#pragma unroll
        for (int w = 0; w < 16; w++) {
            s += sred[w * 32 + t];
            s2 += sred[512 + w * 32 + t];
        }
        atomicAdd(&d_bnsum3[lvl][q * 32 + t], s);
        atomicAdd(&d_bnsq3[lvl][q * 32 + t], s2);
    }
}

// ========== mega topk: BN + score + sort + readout + remap + scan + fill ==========
// Emits d_klocal/d_ksc (+ d_bnA/d_bnB from graph 0); NO feature materialization.
__global__ __launch_bounds__(1024) void k_topk(const float* __restrict__ X,
                                               const float* __restrict__ gamma,
                                               const float* __restrict__ beta,
                                               const float* __restrict__ att,
                                               int nper, int k, int ntot, int lvl,
                                               int do_remap) {
    extern __shared__ int rk[];  // EPG ints
    __shared__ float sscale[128], sshift[128], satt[128];
    __shared__ float score[512];
    __shared__ unsigned long long key[512];
    __shared__ short klocal[512];
    __shared__ float ksc[512];
    __shared__ float red[2048];
    __shared__ int o2n[512];
    __shared__ int scnt[512];
    __shared__ float dv[512];
    __shared__ int wtmp[16], wexcl[16];
    const int g = blockIdx.x, t = threadIdx.x, wid = t >> 5, lane = t & 31;

    if (t < 128) {
        float inv_n = 1.f / (float)ntot;
        float mu = d_bnsum3[lvl][t] * inv_n;
        float var = d_bnsq3[lvl][t] * inv_n - mu * mu;
        float sc = gamma[t] * rsqrtf(var + BN_EPS);
        sscale[t] = sc;
        sshift[t] = beta[t] - mu * sc;
        satt[t] = att[t];
        if (g == 0) {
            d_bnA[lvl][t] = sc;
            d_bnB[lvl][t] = beta[t] - mu * sc;
        }
    }
    if (t < 512) { o2n[t] = -1; scnt[t] = 0; }
    __syncthreads();

    const long long rb = (long long)g * nper;
    const float ainv = d_attinv3[lvl];
    for (int node = wid; node < nper; node += 32) {
        float4 v = ((const float4*)(X + (rb + node) * 128))[lane];
        int c = lane * 4;
        float h0 = fmaxf(fmaf(v.x, sscale[c], sshift[c]), 0.f);
        float h1 = fmaxf(fmaf(v.y, sscale[c + 1], sshift[c + 1]), 0.f);
        float h2 = fmaxf(fmaf(v.z, sscale[c + 2], sshift[c + 2]), 0.f);
        float h3 = fmaxf(fmaf(v.w, sscale[c + 3], sshift[c + 3]), 0.f);
        float dot = h0 * satt[c] + h1 * satt[c + 1] + h2 * satt[c + 2] + h3 * satt[c + 3];
#pragma unroll
        for (int o = 16; o > 0; o >>= 1) dot += __shfl_xor_sync(0xffffffffu, dot, o);
        if (lane == 0) score[node] = tanhf(dot * ainv);
    }
    __syncthreads();

    if (t < 512) {
        unsigned long long kk = 0xFFFFFFFFFFFFFFFFull;
        if (t < nper) {
            unsigned fu = __float_as_uint(score[t]);
            unsigned asc = (fu & 0x80000000u) ? ~fu : (fu | 0x80000000u);
            kk = ((unsigned long long)(~asc) << 32) | (unsigned)t;
        }
        key[t] = kk;
    }
    __syncthreads();
    for (int sz = 2; sz <= 512; sz <<= 1) {
        for (int j = sz >> 1; j > 0; j >>= 1) {
            if (t < 512) {
                int ixj = t ^ j;
                if (ixj > t) {
                    bool up = ((t & sz) == 0);
                    unsigned long long a = key[t], b = key[ixj];
                    if ((a > b) == up) {
                        key[t] = b;
                        key[ixj] = a;
                    }
                }
            }
            __syncthreads();
        }
    }
    if (t < k) {
        int local = (int)(unsigned)(key[t] & 0xffffffffull);
        o2n[local] = t;
        klocal[t] = (short)local;
        float s = score[local];
        ksc[t] = s;
        d_klocal[(g << 9) + t] = local;
        d_ksc[(g << 9) + t] = s;
    }
    __syncthreads();

    // readout (on-the-fly gather; values identical to the old newh computation)
    const int c = t & 127;
    const float sc = sscale[c], sh = sshift[c];
    float mx = -3.4e38f, sm = 0.f;
    for (int j = t >> 7; j < k; j += 8) {
        float raw = X[(rb + klocal[j]) * 128 + c];
        float val = fmaxf(fmaf(raw, sc, sh), 0.f) * ksc[j];
        mx = fmaxf(mx, val);
        sm += val;
    }
    red[t] = mx;
    red[1024 + t] = sm;
    __syncthreads();
    if (t < 128) {
        float m = red[t], s = red[1024 + t];
#pragma unroll
        for (int i = 1; i < 8; i++) {
            m = fmaxf(m, red[t + 128 * i]);
            s += red[1024 + t + 128 * i];
        }
        float* o = d_read + lvl * NG * 256 + g * 256;
        o[t] = m;
        o[128 + t] = s / (float)k;
    }
    if (!do_remap) return;

    const int e0 = g * EPG;
    for (int i = t; i < EPG; i += 1024) {
        int r = -1;
        if (d_em[e0 + i]) {
            int s2 = o2n[d_srcE[e0 + i]];
            int d2 = o2n[d_dstE[e0 + i]];
            if (s2 >= 0 && d2 >= 0) {
                r = atomicAdd(&scnt[d2], 1);
                d_srcE[e0 + i] = s2;
                d_dstE[e0 + i] = d2;
            } else {
                d_em[e0 + i] = 0;
            }
        }
        rk[i] = r;
    }
    __syncthreads();

    int v = 0;
    if (t < 512) v = (t < k) ? scnt[t] : 0;
    int incl = v;
#pragma unroll
    for (int o = 1; o < 32; o <<= 1) {
        int y = __shfl_up_sync(0xffffffffu, incl, o);
        if (lane >= o) incl += y;
    }
    if (t < 512 && lane == 31) wtmp[wid] = incl;
    __syncthreads();
    if (t < 16) {
        int w = wtmp[t], s = w;
#pragma unroll
        for (int o = 1; o < 16; o <<= 1) {
            int y = __shfl_up_sync(0x0000ffffu, s, o);
            if (t >= o) s += y;
        }
        wexcl[t] = s - w;
    }
    __syncthreads();
    if (t < 512) {
        int excl = incl - v + wexcl[wid];
        if (t < k) {
            int node = (g << 9) + t;
            d_coff[node] = e0 + excl;
            d_indeg[node] = v;
            float di = rsqrtf((float)v + 1.f);
            d_dinv[node] = di;
            dv[t] = di;
            scnt[t] = excl;
        }
    }
    __syncthreads();

    for (int i = t; i < EPG; i += 1024) {
        if (rk[i] >= 0) {
            int s2 = d_srcE[e0 + i], d2 = d_dstE[e0 + i];
            union { struct { int s; float c; } p; long long ll; } u;
            u.p.s = s2;
            u.p.c = dv[s2] * dv[d2];
            d_csr[e0 + scnt[d2] + rk[i]] = u.ll;
        }
    }
}

// ================= final MLP =================
__global__ __launch_bounds__(128) void k_final(const float* __restrict__ Wl1,
                                               const float* __restrict__ bl1,
                                               const float* __restrict__ Wl2,
                                               const float* __restrict__ bl2,
                                               float* __restrict__ out) {
    __shared__ float s[256];
    __shared__ float hid[128];
    int g = blockIdx.x, t = threadIdx.x;
    for (int i = t; i < 256; i += 128)
        s[i] = d_read[0 * NG * 256 + g * 256 + i] + d_read[1 * NG * 256 + g * 256 + i] +
               d_read[2 * NG * 256 + g * 256 + i];
    __syncthreads();
    float acc = bl1[t];
#pragma unroll 8
    for (int j = 0; j < 256; j++) acc += s[j] * Wl1[j * 128 + t];
    hid[t] = fmaxf(acc, 0.f);
    __syncthreads();
    if (t < 64) {
        int o = t >> 5, lane = t & 31;
        float p = 0.f;
#pragma unroll
        for (int j = lane; j < 128; j += 32) p += hid[j] * Wl2[j * 2 + o];
#pragma unroll
        for (int off = 16; off > 0; off >>= 1) p += __shfl_xor_sync(0xffffffffu, p, off);
        if (lane == 0) out[g * 2 + o] = p + bl2[o];
    }
}

// ================= orchestration =================
extern "C" void kernel_launch(void* const* d_in, const int* in_sizes, int n_in,
                              void* d_out, int out_size) {
    (void)in_sizes; (void)n_in; (void)out_size;
    const float* x = (const float*)d_in[0];
    const int* ei = (const int*)d_in[1];
    const float* Wp = (const float*)d_in[3];
    const float* bp = (const float*)d_in[4];
    const float* Wc[3] = {(const float*)d_in[5], (const float*)d_in[10], (const float*)d_in[15]};
    const float* bc[3] = {(const float*)d_in[6], (const float*)d_in[11], (const float*)d_in[16]};
    const float* gc[3] = {(const float*)d_in[7], (const float*)d_in[12], (const float*)d_in[17]};
    const float* be[3] = {(const float*)d_in[8], (const float*)d_in[13], (const float*)d_in[18]};
    const float* at[3] = {(const float*)d_in[9], (const float*)d_in[14], (const float*)d_in[19]};
    const float* Wl1 = (const float*)d_in[20];
    const float* bl1 = (const float*)d_in[21];
    const float* Wl2 = (const float*)d_in[22];
    const float* bl2 = (const float*)d_in[23];

    float *bufA, *bufB;
    cudaGetSymbolAddress((void**)&bufA, d_bufA);
    cudaGetSymbolAddress((void**)&bufB, d_bufB);

    cudaFuncSetAttribute(k_mmg, cudaFuncAttributeMaxDynamicSharedMemorySize, MM_SMEM);
    cudaFuncSetAttribute(k_mm2, cudaFuncAttributeMaxDynamicSharedMemorySize, MM_SMEM);
    cudaFuncSetAttribute(k_conv, cudaFuncAttributeMaxDynamicSharedMemorySize, 65536);
    cudaFuncSetAttribute(k_topk, cudaFuncAttributeMaxDynamicSharedMemorySize, 40960);

    // bufB = GEMM output (xl), bufA = conv output (X), every level
    k_init<<<NG, 512>>>(ei, at[0], at[1], at[2]);
    k_mm2<<<N0TOT / 128, 256, MM_SMEM>>>(x, Wp, bp, Wc[0], bufB);
    k_conv<<<dim3(NG, 4), 512, NPER0 * 32 * sizeof(float)>>>(bufB, bufA, bc[0], NPER0, 0);
    k_topk<<<NG, 1024, EPG * sizeof(int)>>>(bufA, gc[0], be[0], at[0],
                                            NPER0, K1C, N0TOT, 0, 1);
    k_mmg<<<N1TOT / 128, 256, MM_SMEM>>>(bufA, Wc[1], bufB, K1C, NPER0, 0);
    k_conv<<<dim3(NG, 4), 512, K1C * 32 * sizeof(float)>>>(bufB, bufA, bc[1], K1C, 1);
    k_topk<<<NG, 1024, EPG * sizeof(int)>>>(bufA, gc[1], be[1], at[1],
                                            K1C, K2C, N1TOT, 1, 1);
    k_mmg<<<N2TOT / 128, 256, MM_SMEM>>>(bufA, Wc[2], bufB, K2C, K1C, 1);
    k_conv<<<dim3(NG, 4), 512, K2C * 32 * sizeof(float)>>>(bufB, bufA, bc[2], K2C, 2);
    k_topk<<<NG, 1024, EPG * sizeof(int)>>>(bufA, gc[2], be[2], at[2],
                                            K2C, K3C, N2TOT, 2, 0);
    k_final<<<NG, 128>>>(Wl1, bl1, Wl2, bl2, (float*)d_out);
}

// round 17
// speedup vs baseline: 1.0655x; 1.0655x over previous
#include <cuda_runtime.h>
#include <cuda_bf16.h>
#include <cstdint>

#define NG 128
#define NPER0 512
#define N0TOT 65536
#define E_TOT 1048576
#define EPG 8192
#define INC 100
#define HIDC 128
#define K1C 410
#define K2C 328
#define K3C 263
#define N1TOT (NG*K1C)
#define N2TOT (NG*K2C)
#define BN_EPS 1e-5f

#define LDB 136            // bf16 units per smem row (pad: conflict-free fragments)
#define TILE_ELEMS (128*LDB)
#define MM_SMEM (4*TILE_ELEMS*2)   // 4 bf16 tiles = 139264 B

// ---------------- device scratch ----------------
__device__ __align__(16) float d_bufA[N0TOT*HIDC];
__device__ __align__(16) float d_bufB[N0TOT*HIDC];
__device__ int   d_indeg[NG*NPER0];
__device__ int   d_coff[NG*NPER0];
__device__ float d_dinv[NG*NPER0];
__device__ int   d_srcE[E_TOT];
__device__ int   d_dstE[E_TOT];
__device__ unsigned char d_em[E_TOT];
__device__ long long d_csr[E_TOT];
__device__ __align__(16) float d_bnsum3[3][HIDC];
__device__ __align__(16) float d_bnsq3[3][HIDC];
__device__ float d_attinv3[3];
__device__ __align__(16) float d_read[3*NG*2*HIDC];

// ---------------- mma.sync bf16 helper (sm_80+, valid on sm_103) ----------------
__device__ __forceinline__ void mma_bf16(float* d, const uint32_t* a, const uint32_t* b) {
    asm volatile(
        "mma.sync.aligned.m16n8k16.row.col.f32.bf16.bf16.f32 "
        "{%0,%1,%2,%3},{%4,%5,%6,%7},{%8,%9},{%0,%1,%2,%3};"
        : "+f"(d[0]), "+f"(d[1]), "+f"(d[2]), "+f"(d[3])
        : "r"(a[0]), "r"(a[1]), "r"(a[2]), "r"(a[3]), "r"(b[0]), "r"(b[1]));
}
__device__ __forceinline__ uint32_t pack_hi(float x, float y) {
    __nv_bfloat162 p = __floats2bfloat162_rn(x, y);
    return *(uint32_t*)&p;
}

// frag compute core: acc[16][4] over warp tile 64x32, K-steps [0, nk16)
__device__ __forceinline__ void mm_core(const __nv_bfloat16* Ah, const __nv_bfloat16* Al,
                                        const __nv_bfloat16* Bh, const __nv_bfloat16* Bl,
                                        int mw, int nw, int g, int tg, int nk16,
                                        float acc[16][4]) {
#pragma unroll
    for (int pass = 0; pass < 3; pass++) {
        const __nv_bfloat16* As = (pass == 2) ? Al : Ah;
        const __nv_bfloat16* Bs = (pass == 1) ? Bl : Bh;
        for (int ks = 0; ks < nk16; ks++) {
            const int kb = ks * 16 + tg * 2;
            uint32_t a[4][4], b[4][2];
#pragma unroll
            for (int mt = 0; mt < 4; mt++) {
                int r = mw + mt * 16 + g;
                a[mt][0] = *(const uint32_t*)&As[r * LDB + kb];
                a[mt][1] = *(const uint32_t*)&As[(r + 8) * LDB + kb];
                a[mt][2] = *(const uint32_t*)&As[r * LDB + kb + 8];
                a[mt][3] = *(const uint32_t*)&As[(r + 8) * LDB + kb + 8];
            }
#pragma unroll
            for (int nt = 0; nt < 4; nt++) {
                int n = nw + nt * 8 + g;
                b[nt][0] = *(const uint32_t*)&Bs[n * LDB + kb];
                b[nt][1] = *(const uint32_t*)&Bs[n * LDB + kb + 8];
            }
#pragma unroll
            for (int mt = 0; mt < 4; mt++)
#pragma unroll
                for (int nt = 0; nt < 4; nt++) mma_bf16(acc[mt * 4 + nt], a[mt], b[nt]);
        }
    }
}

// ================= plain GEMM (K=128): C[M,128] = A[M,128] @ W[128,128] ==========
__global__ __launch_bounds__(256) void k_mm(const float* __restrict__ A,
                                            const float* __restrict__ W,
                                            float* __restrict__ C) {
    extern __shared__ char sm[];
    __nv_bfloat16* Ah = (__nv_bfloat16*)sm;
    __nv_bfloat16* Al = Ah + TILE_ELEMS;
    __nv_bfloat16* Bh = Al + TILE_ELEMS;
    __nv_bfloat16* Bl = Bh + TILE_ELEMS;
    const int t = threadIdx.x, w = t >> 5, lane = t & 31, g = lane >> 2, tg = lane & 3;
    const long long row0 = (long long)blockIdx.x * 128;

    for (int i = t; i < 128 * 64; i += 256) {
        int r = i >> 6, k2 = (i & 63) * 2;
        float2 v = *(const float2*)&A[(row0 + r) * 128 + k2];
        __nv_bfloat16 hx = __float2bfloat16(v.x), hy = __float2bfloat16(v.y);
        *(uint32_t*)&Ah[r * LDB + k2] = pack_hi(v.x, v.y);
        *(uint32_t*)&Al[r * LDB + k2] =
            pack_hi(v.x - __bfloat162float(hx), v.y - __bfloat162float(hy));
    }
    for (int i = t; i < 128 * 128; i += 256) {
        int k = i >> 7, n = i & 127;
        float v = W[i];
        __nv_bfloat16 h = __float2bfloat16(v);
        Bh[n * LDB + k] = h;
        Bl[n * LDB + k] = __float2bfloat16(v - __bfloat162float(h));
    }
    __syncthreads();

    const int mw = (w & 1) * 64, nw = (w >> 1) * 32;
    float acc[16][4];
#pragma unroll
    for (int i = 0; i < 16; i++)
#pragma unroll
        for (int j = 0; j < 4; j++) acc[i][j] = 0.f;

    mm_core(Ah, Al, Bh, Bl, mw, nw, g, tg, 8, acc);

#pragma unroll
    for (int mt = 0; mt < 4; mt++)
#pragma unroll
        for (int nt = 0; nt < 4; nt++) {
            long long r = row0 + mw + mt * 16 + g;
            int c = nw + nt * 8 + tg * 2;
            float* ap = acc[mt * 4 + nt];
            *(float2*)&C[r * 128 + c] = make_float2(ap[0], ap[1]);
            *(float2*)&C[(r + 8) * 128 + c] = make_float2(ap[2], ap[3]);
        }
}

// ====== fused: h = relu(x@Wp + bp); C = h @ W1  (K phase A padded 100->112) ======
__global__ __launch_bounds__(256) void k_mm2(const float* __restrict__ X,
                                             const float* __restrict__ Wp,
                                             const float* __restrict__ bp,
                                             const float* __restrict__ W1,
                                             float* __restrict__ C) {
    extern __shared__ char sm[];
    __nv_bfloat16* Ah = (__nv_bfloat16*)sm;
    __nv_bfloat16* Al = Ah + TILE_ELEMS;
    __nv_bfloat16* Bh = Al + TILE_ELEMS;
    __nv_bfloat16* Bl = Bh + TILE_ELEMS;
    __shared__ float sbias[128];
    const int t = threadIdx.x, w = t >> 5, lane = t & 31, g = lane >> 2, tg = lane & 3;
    const long long row0 = (long long)blockIdx.x * 128;

    if (t < 128) sbias[t] = bp[t];
    // zero pad region k in [96,112) of all 4 tiles
    for (int i = t; i < 128 * 16; i += 256) {
        int r = i >> 4, k = 96 + (i & 15);
        Ah[r * LDB + k] = __nv_bfloat16(0.f);
        Al[r * LDB + k] = __nv_bfloat16(0.f);
        Bh[r * LDB + k] = __nv_bfloat16(0.f);
        Bl[r * LDB + k] = __nv_bfloat16(0.f);
    }
    __syncthreads();
    for (int i = t; i < 128 * 50; i += 256) {   // x: 128 rows x 100 cols (50 float2)
        int r = i / 50, k2 = (i - r * 50) * 2;
        float2 v = *(const float2*)&X[(row0 + r) * INC + k2];
        __nv_bfloat16 hx = __float2bfloat16(v.x), hy = __float2bfloat16(v.y);
        *(uint32_t*)&Ah[r * LDB + k2] = pack_hi(v.x, v.y);
        *(uint32_t*)&Al[r * LDB + k2] =
            pack_hi(v.x - __bfloat162float(hx), v.y - __bfloat162float(hy));
    }
    for (int i = t; i < INC * 128; i += 256) {
        int k = i >> 7, n = i & 127;
        float v = Wp[i];
        __nv_bfloat16 h = __float2bfloat16(v);
        Bh[n * LDB + k] = h;
        Bl[n * LDB + k] = __float2bfloat16(v - __bfloat162float(h));
    }
    __syncthreads();

    const int mw = (w & 1) * 64, nw = (w >> 1) * 32;
    float acc[16][4];
#pragma unroll
    for (int i = 0; i < 16; i++)
#pragma unroll
        for (int j = 0; j < 4; j++) acc[i][j] = 0.f;

    mm_core(Ah, Al, Bh, Bl, mw, nw, g, tg, 7, acc);   // 112/16 = 7 ksteps
    __syncthreads();   // all smem reads done before overwrite

    // bias+relu, split h -> Ah/Al (k index = output col); then load W1 -> Bh/Bl
#pragma unroll
    for (int mt = 0; mt < 4; mt++)
#pragma unroll
        for (int nt = 0; nt < 4; nt++) {
            int r = mw + mt * 16 + g;
            int c = nw + nt * 8 + tg * 2;
            float* ap = acc[mt * 4 + nt];
            float v0 = fmaxf(ap[0] + sbias[c], 0.f);
            float v1 = fmaxf(ap[1] + sbias[c + 1], 0.f);
            float v2 = fmaxf(ap[2] + sbias[c], 0.f);
            float v3 = fmaxf(ap[3] + sbias[c + 1], 0.f);
            __nv_bfloat16 h0 = __float2bfloat16(v0), h1 = __float2bfloat16(v1);
            __nv_bfloat16 h2 = __float2bfloat16(v2), h3 = __float2bfloat16(v3);
            *(uint32_t*)&Ah[r * LDB + c] = pack_hi(v0, v1);
            *(uint32_t*)&Al[r * LDB + c] =
                pack_hi(v0 - __bfloat162float(h0), v1 - __bfloat162float(h1));
            *(uint32_t*)&Ah[(r + 8) * LDB + c] = pack_hi(v2, v3);
            *(uint32_t*)&Al[(r + 8) * LDB + c] =
                pack_hi(v2 - __bfloat162float(h2), v3 - __bfloat162float(h3));
            ap[0] = ap[1] = ap[2] = ap[3] = 0.f;
        }
    for (int i = t; i < 128 * 128; i += 256) {
        int k = i >> 7, n = i & 127;
        float v = W1[i];
        __nv_bfloat16 h = __float2bfloat16(v);
        Bh[n * LDB + k] = h;
        Bl[n * LDB + k] = __float2bfloat16(v - __bfloat162float(h));
    }
    __syncthreads();

    mm_core(Ah, Al, Bh, Bl, mw, nw, g, tg, 8, acc);

#pragma unroll
    for (int mt = 0; mt < 4; mt++)
#pragma unroll
        for (int nt = 0; nt < 4; nt++) {
            long long r = row0 + mw + mt * 16 + g;
            int c = nw + nt * 8 + tg * 2;
            float* ap = acc[mt * 4 + nt];
            *(float2*)&C[r * 128 + c] = make_float2(ap[0], ap[1]);
            *(float2*)&C[(r + 8) * 128 + c] = make_float2(ap[2], ap[3]);
        }
}

// ================= init: edge load + count + scan + CSR fill (level 0) ===========
__global__ __launch_bounds__(512) void k_init(const int* __restrict__ ei,
                                              const float* __restrict__ at0,
                                              const float* __restrict__ at1,
                                              const float* __restrict__ at2) {
    __shared__ int scnt[512];
    __shared__ int rk[EPG];
    __shared__ float dv[512];
    __shared__ int wtmp[16], wexcl[16];
    const int g = blockIdx.x, t = threadIdx.x, lane = t & 31, wid = t >> 5;
    scnt[t] = 0;
    if (g == 0) {
        if (t < 384) {
            ((float*)d_bnsum3)[t] = 0.f;
            ((float*)d_bnsq3)[t] = 0.f;
        }
        if (wid >= 13) {
            const float* ap = (wid == 13) ? at0 : (wid == 14) ? at1 : at2;
            float s = 0.f;
#pragma unroll
            for (int q = 0; q < 4; q++) { float v = ap[lane + 32 * q]; s += v * v; }
#pragma unroll
            for (int o = 16; o > 0; o >>= 1) s += __shfl_xor_sync(0xffffffffu, s, o);
            if (lane == 0) d_attinv3[wid - 13] = rsqrtf(s);
        }
    }
    __syncthreads();
    const int e0 = g * EPG;
    for (int i = t; i < EPG; i += 512) {
        int sl = ei[e0 + i] - (g << 9);
        int dl = ei[E_TOT + e0 + i] - (g << 9);
        rk[i] = atomicAdd(&scnt[dl], 1);
        d_srcE[e0 + i] = sl;
        d_dstE[e0 + i] = dl;
        d_em[e0 + i] = 1;
    }
    __syncthreads();
    int v = scnt[t];
    int incl = v;
#pragma unroll
    for (int o = 1; o < 32; o <<= 1) {
        int y = __shfl_up_sync(0xffffffffu, incl, o);
        if (lane >= o) incl += y;
    }
    if (lane == 31) wtmp[wid] = incl;
    __syncthreads();
    if (t < 16) {
        int w = wtmp[t], s = w;
#pragma unroll
        for (int o = 1; o < 16; o <<= 1) {
            int y = __shfl_up_sync(0x0000ffffu, s, o);
            if (t >= o) s += y;
        }
        wexcl[t] = s - w;
    }
    __syncthreads();
    int excl = incl - v + wexcl[wid];
    {
        int node = (g << 9) + t;
        d_coff[node] = e0 + excl;
        d_indeg[node] = v;
        float di = rsqrtf((float)v + 1.f);
        d_dinv[node] = di;
        dv[t] = di;
        scnt[t] = excl;
    }
    __syncthreads();
    for (int i = t; i < EPG; i += 512) {
        int sl = d_srcE[e0 + i], dl = d_dstE[e0 + i];
        int slot = scnt[dl] + rk[i];
        union { struct { int s; float c; } p; long long ll; } u;
        u.p.s = sl;
        u.p.c = dv[sl] * dv[dl];
        d_csr[e0 + slot] = u.ll;
    }
}

// ================= conv: quarter-channel smem gather + fused BN stats =====
__global__ __launch_bounds__(512) void k_conv(const float* __restrict__ xl,
                                              float* __restrict__ out,
                                              const float* __restrict__ bias,
                                              int nper, int lvl) {
    extern __shared__ float sf[];
    __shared__ float sred[1024];
    const int g = blockIdx.x, q = blockIdx.y;
    const int t = threadIdx.x, wid = t >> 5, lane = t & 31;
    const long long rb = (long long)g * nper;

    for (int idx = t; idx < nper * 8; idx += 512) {
        int r = idx >> 3, c4 = idx & 7;
        ((float4*)sf)[r * 8 + c4] = ((const float4*)(xl + (rb + r) * 128 + q * 32))[c4];
    }
    __syncthreads();

    const int ch = q * 32 + lane;
    const float bb = bias[ch];
    float bs = 0.f, bq = 0.f;
    for (int node = wid; node < nper; node += 16) {
        int gnode = (g << 9) + node;
        int base = d_coff[gnode];
        int cnt = d_indeg[gnode];
        float a = 0.f;
#pragma unroll 4
        for (int j = 0; j < cnt; j++) {
            long long ll = __ldg(&d_csr[base + j]);
            int sl = (int)(ll & 0xffffffffll);
            float w = __int_as_float((int)(ll >> 32));
            a += w * sf[sl * 32 + lane];
        }
        float di = d_dinv[gnode];
        a += di * di * sf[node * 32 + lane] + bb;
        out[(rb + node) * 128 + ch] = a;
        bs += a;
        bq += a * a;
    }
    sred[wid * 32 + lane] = bs;
    sred[512 + wid * 32 + lane] = bq;
    __syncthreads();
    if (t < 32) {
        float s = 0.f, s2 = 0.f;
#pragma unroll
        for (int w = 0; w < 16; w++) {
            s += sred[w * 32 + t];
            s2 += sred[512 + w * 32 + t];
        }
        atomicAdd(&d_bnsum3[lvl][q * 32 + t], s);
        atomicAdd(&d_bnsq3[lvl][q * 32 + t], s2);
    }
}

// ========== mega topk: BN + score + hybrid-bitonic sort + gather + readout + remap ==========
__global__ __launch_bounds__(1024) void k_topk(const float* __restrict__ X,
                                               float* __restrict__ newh,
                                               const float* __restrict__ gamma,
                                               const float* __restrict__ beta,
                                               const float* __restrict__ att,
                                               int nper, int kpar, int ntot, int lvl,
                                               int do_remap) {
    extern __shared__ int rk[];  // EPG ints
    __shared__ float sscale[128], sshift[128], satt[128];
    __shared__ float score[512];
    __shared__ unsigned long long skey[512];
    __shared__ short klocal[512];
    __shared__ float ksc[512];
    __shared__ float red[2048];
    __shared__ int o2n[512];
    __shared__ int scnt[512];
    __shared__ float dv[512];
    __shared__ int wtmp[16], wexcl[16];
    const int g = blockIdx.x, t = threadIdx.x, wid = t >> 5, lane = t & 31;

    if (t < 128) {
        float inv_n = 1.f / (float)ntot;
        float mu = d_bnsum3[lvl][t] * inv_n;
        float var = d_bnsq3[lvl][t] * inv_n - mu * mu;
        float sc = gamma[t] * rsqrtf(var + BN_EPS);
        sscale[t] = sc;
        sshift[t] = beta[t] - mu * sc;
        satt[t] = att[t];
    }
    if (t < 512) { o2n[t] = -1; scnt[t] = 0; }
    __syncthreads();

    const long long rb = (long long)g * nper;
    const float ainv = d_attinv3[lvl];

    // ---- score: warp per node, coeffs hoisted, 4 nodes in flight ----
    {
        const int c4 = lane * 4;
        const float s0 = sscale[c4], s1 = sscale[c4 + 1], s2 = sscale[c4 + 2], s3 = sscale[c4 + 3];
        const float h0 = sshift[c4], h1 = sshift[c4 + 1], h2 = sshift[c4 + 2], h3 = sshift[c4 + 3];
        const float a0 = satt[c4], a1 = satt[c4 + 1], a2 = satt[c4 + 2], a3 = satt[c4 + 3];
        for (int n0 = wid; n0 < nper; n0 += 128) {
            float d0 = 0.f, d1 = 0.f, d2 = 0.f, d3 = 0.f;
            const bool b1 = (n0 + 32) < nper, b2 = (n0 + 64) < nper, b3 = (n0 + 96) < nper;
            {
                float4 v = ((const float4*)(X + (rb + n0) * 128))[lane];
                d0 = fmaxf(fmaf(v.x, s0, h0), 0.f) * a0 + fmaxf(fmaf(v.y, s1, h1), 0.f) * a1 +
                     fmaxf(fmaf(v.z, s2, h2), 0.f) * a2 + fmaxf(fmaf(v.w, s3, h3), 0.f) * a3;
            }
            if (b1) {
                float4 v = ((const float4*)(X + (rb + n0 + 32) * 128))[lane];
                d1 = fmaxf(fmaf(v.x, s0, h0), 0.f) * a0 + fmaxf(fmaf(v.y, s1, h1), 0.f) * a1 +
                     fmaxf(fmaf(v.z, s2, h2), 0.f) * a2 + fmaxf(fmaf(v.w, s3, h3), 0.f) * a3;
            }
            if (b2) {
                float4 v = ((const float4*)(X + (rb + n0 + 64) * 128))[lane];
                d2 = fmaxf(fmaf(v.x, s0, h0), 0.f) * a0 + fmaxf(fmaf(v.y, s1, h1), 0.f) * a1 +
                     fmaxf(fmaf(v.z, s2, h2), 0.f) * a2 + fmaxf(fmaf(v.w, s3, h3), 0.f) * a3;
            }
            if (b3) {
                float4 v = ((const float4*)(X + (rb + n0 + 96) * 128))[lane];
                d3 = fmaxf(fmaf(v.x, s0, h0), 0.f) * a0 + fmaxf(fmaf(v.y, s1, h1), 0.f) * a1 +
                     fmaxf(fmaf(v.z, s2, h2), 0.f) * a2 + fmaxf(fmaf(v.w, s3, h3), 0.f) * a3;
            }
#pragma unroll
            for (int o = 16; o > 0; o >>= 1) {
                d0 += __shfl_xor_sync(0xffffffffu, d0, o);
                d1 += __shfl_xor_sync(0xffffffffu, d1, o);
                d2 += __shfl_xor_sync(0xffffffffu, d2, o);
                d3 += __shfl_xor_sync(0xffffffffu, d3, o);
            }
            if (lane == 0) {
                score[n0] = tanhf(d0 * ainv);
                if (b1) score[n0 + 32] = tanhf(d1 * ainv);
                if (b2) score[n0 + 64] = tanhf(d2 * ainv);
                if (b3) score[n0 + 96] = tanhf(d3 * ainv);
            }
        }
    }
    __syncthreads();

    // ---- hybrid bitonic sort: key in register, shfl for j<32, smem for j>=32 ----
    unsigned long long kreg = 0xFFFFFFFFFFFFFFFFull;
    if (t < nper) {
        unsigned fu = __float_as_uint(score[t]);
        unsigned asc = (fu & 0x80000000u) ? ~fu : (fu | 0x80000000u);
        kreg = ((unsigned long long)(~asc) << 32) | (unsigned)t;
    }
    for (int sz = 2; sz <= 512; sz <<= 1) {
        for (int j = sz >> 1; j > 0; j >>= 1) {
            unsigned long long other;
            if (j >= 32) {
                if (t < 512) skey[t] = kreg;
                __syncthreads();
                other = (t < 512) ? skey[t ^ j] : 0ull;
                __syncthreads();
            } else {
                other = __shfl_xor_sync(0xffffffffu, kreg, j);
            }
            if (t < 512) {
                bool up = ((t & sz) == 0);
                bool take_min = (up == ((t & j) == 0));
                bool kmin = kreg < other;
                kreg = (take_min == kmin) ? kreg : other;
            }
        }
    }
    if (t < kpar) {
        int local = (int)(unsigned)(kreg & 0xffffffffull);
        o2n[local] = t;
        klocal[t] = (short)local;
        ksc[t] = score[local];
    }
    __syncthreads();

    // ---- gather + gate + readout (4 rows in flight; same j order as before) ----
    const int c = t & 127;
    const float scg = sscale[c], shg = sshift[c];
    float mx = -3.4e38f, sm = 0.f;
    for (int j0 = t >> 7; j0 < kpar; j0 += 32) {
        const int j1 = j0 + 8, j2 = j0 + 16, j3 = j0 + 24;
        const bool b1 = j1 < kpar, b2 = j2 < kpar, b3 = j3 < kpar;
        float r0 = X[(rb + klocal[j0]) * 128 + c];
        float r1 = b1 ? X[(rb + klocal[j1]) * 128 + c] : 0.f;
        float r2 = b2 ? X[(rb + klocal[j2]) * 128 + c] : 0.f;
        float r3 = b3 ? X[(rb + klocal[j3]) * 128 + c] : 0.f;
        {
            float val = fmaxf(fmaf(r0, scg, shg), 0.f) * ksc[j0];
            if (do_remap) newh[((long long)(g * kpar + j0)) * 128 + c] = val;
            mx = fmaxf(mx, val);
            sm += val;
        }
        if (b1) {
            float val = fmaxf(fmaf(r1, scg, shg), 0.f) * ksc[j1];
            if (do_remap) newh[((long long)(g * kpar + j1)) * 128 + c] = val;
            mx = fmaxf(mx, val);
            sm += val;
        }
        if (b2) {
            float val = fmaxf(fmaf(r2, scg, shg), 0.f) * ksc[j2];
            if (do_remap) newh[((long long)(g * kpar + j2)) * 128 + c] = val;
            mx = fmaxf(mx, val);
            sm += val;
        }
        if (b3) {
            float val = fmaxf(fmaf(r3, scg, shg), 0.f) * ksc[j3];
            if (do_remap) newh[((long long)(g * kpar + j3)) * 128 + c] = val;
            mx = fmaxf(mx, val);
            sm += val;
        }
    }
    red[t] = mx;
    red[1024 + t] = sm;
    __syncthreads();
    if (t < 128) {
        float m = red[t], s = red[1024 + t];
#pragma unroll
        for (int i = 1; i < 8; i++) {
            m = fmaxf(m, red[t + 128 * i]);
            s += red[1024 + t + 128 * i];
        }
        float* o = d_read + lvl * NG * 256 + g * 256;
        o[t] = m;
        o[128 + t] = s / (float)kpar;
    }
    if (!do_remap) return;

    // ---- remap + count; pack (s2:9 | d2:9<<9 | rank:13<<18) into rk ----
    const int e0 = g * EPG;
    for (int i = t; i < EPG; i += 1024) {
        int r = -1;
        if (d_em[e0 + i]) {
            int s2 = o2n[d_srcE[e0 + i]];
            int d2 = o2n[d_dstE[e0 + i]];
            if (s2 >= 0 && d2 >= 0) {
                int rank = atomicAdd(&scnt[d2], 1);
                d_srcE[e0 + i] = s2;
                d_dstE[e0 + i] = d2;
                r = s2 | (d2 << 9) | (rank << 18);
            } else {
                d_em[e0 + i] = 0;
            }
        }
        rk[i] = r;
    }
    __syncthreads();

    // ---- scan kpar counts -> offsets, dinv ----
    int v = 0;
    if (t < 512) v = (t < kpar) ? scnt[t] : 0;
    int incl = v;
#pragma unroll
    for (int o = 1; o < 32; o <<= 1) {
        int y = __shfl_up_sync(0xffffffffu, incl, o);
        if (lane >= o) incl += y;
    }
    if (t < 512 && lane == 31) wtmp[wid] = incl;
    __syncthreads();
    if (t < 16) {
        int w = wtmp[t], s = w;
#pragma unroll
        for (int o = 1; o < 16; o <<= 1) {
            int y = __shfl_up_sync(0x0000ffffu, s, o);
            if (t >= o) s += y;
        }
        wexcl[t] = s - w;
    }
    __syncthreads();
    if (t < 512) {
        int excl = incl - v + wexcl[wid];
        if (t < kpar) {
            int node = (g << 9) + t;
            d_coff[node] = e0 + excl;
            d_indeg[node] = v;
            float di = rsqrtf((float)v + 1.f);
            d_dinv[node] = di;
            dv[t] = di;
            scnt[t] = excl;
        }
    }
    __syncthreads();

    // ---- fill CSR from packed rk (no global re-reads) ----
    for (int i = t; i < EPG; i += 1024) {
        int r = rk[i];
        if (r >= 0) {
            int s2 = r & 511, d2 = (r >> 9) & 511, rank = r >> 18;
            union { struct { int s; float c; } p; long long ll; } u;
            u.p.s = s2;
            u.p.c = dv[s2] * dv[d2];
            d_csr[e0 + scnt[d2] + rank] = u.ll;
        }
    }
}

// ================= final MLP =================
__global__ __launch_bounds__(128) void k_final(const float* __restrict__ Wl1,
                                               const float* __restrict__ bl1,
                                               const float* __restrict__ Wl2,
                                               const float* __restrict__ bl2,
                                               float* __restrict__ out) {
    __shared__ float s[256];
    __shared__ float hid[128];
    int g = blockIdx.x, t = threadIdx.x;
    for (int i = t; i < 256; i += 128)
        s[i] = d_read[0 * NG * 256 + g * 256 + i] + d_read[1 * NG * 256 + g * 256 + i] +
               d_read[2 * NG * 256 + g * 256 + i];
    __syncthreads();
    float acc = bl1[t];
#pragma unroll 8
    for (int j = 0; j < 256; j++) acc += s[j] * Wl1[j * 128 + t];
    hid[t] = fmaxf(acc, 0.f);
    __syncthreads();
    if (t < 64) {
        int o = t >> 5, lane = t & 31;
        float p = 0.f;
#pragma unroll
        for (int j = lane; j < 128; j += 32) p += hid[j] * Wl2[j * 2 + o];
#pragma unroll
        for (int off = 16; off > 0; off >>= 1) p += __shfl_xor_sync(0xffffffffu, p, off);
        if (lane == 0) out[g * 2 + o] = p + bl2[o];
    }
}

// ================= orchestration =================
extern "C" void kernel_launch(void* const* d_in, const int* in_sizes, int n_in,
                              void* d_out, int out_size) {
    (void)in_sizes; (void)n_in; (void)out_size;
    const float* x = (const float*)d_in[0];
    const int* ei = (const int*)d_in[1];
    const float* Wp = (const float*)d_in[3];
    const float* bp = (const float*)d_in[4];
    const float* Wc[3] = {(const float*)d_in[5], (const float*)d_in[10], (const float*)d_in[15]};
    const float* bc[3] = {(const float*)d_in[6], (const float*)d_in[11], (const float*)d_in[16]};
    const float* gc[3] = {(const float*)d_in[7], (const float*)d_in[12], (const float*)d_in[17]};
    const float* be[3] = {(const float*)d_in[8], (const float*)d_in[13], (const float*)d_in[18]};
    const float* at[3] = {(const float*)d_in[9], (const float*)d_in[14], (const float*)d_in[19]};
    const float* Wl1 = (const float*)d_in[20];
    const float* bl1 = (const float*)d_in[21];
    const float* Wl2 = (const float*)d_in[22];
    const float* bl2 = (const float*)d_in[23];

    float *bufA, *bufB;
    cudaGetSymbolAddress((void**)&bufA, d_bufA);
    cudaGetSymbolAddress((void**)&bufB, d_bufB);

    cudaFuncSetAttribute(k_mm, cudaFuncAttributeMaxDynamicSharedMemorySize, MM_SMEM);
    cudaFuncSetAttribute(k_mm2, cudaFuncAttributeMaxDynamicSharedMemorySize, MM_SMEM);
    cudaFuncSetAttribute(k_conv, cudaFuncAttributeMaxDynamicSharedMemorySize, 65536);
    cudaFuncSetAttribute(k_topk, cudaFuncAttributeMaxDynamicSharedMemorySize, 40960);

    k_init<<<NG, 512>>>(ei, at[0], at[1], at[2]);
    k_mm2<<<N0TOT / 128, 256, MM_SMEM>>>(x, Wp, bp, Wc[0], bufB);
    k_conv<<<dim3(NG, 4), 512, NPER0 * 32 * sizeof(float)>>>(bufB, bufA, bc[0], NPER0, 0);
    k_topk<<<NG, 1024, EPG * sizeof(int)>>>(bufA, bufB, gc[0], be[0], at[0],
                                            NPER0, K1C, N0TOT, 0, 1);
    k_mm<<<N1TOT / 128, 256, MM_SMEM>>>(bufB, Wc[1], bufA);
    k_conv<<<dim3(NG, 4), 512, K1C * 32 * sizeof(float)>>>(bufA, bufB, bc[1], K1C, 1);
    k_topk<<<NG, 1024, EPG * sizeof(int)>>>(bufB, bufA, gc[1], be[1], at[1],
                                            K1C, K2C, N1TOT, 1, 1);
    k_mm<<<N2TOT / 128, 256, MM_SMEM>>>(bufA, Wc[2], bufB);
    k_conv<<<dim3(NG, 4), 512, K2C * 32 * sizeof(float)>>>(bufB, bufA, bc[2], K2C, 2);
    k_topk<<<NG, 1024, EPG * sizeof(int)>>>(bufA, bufB, gc[2], be[2], at[2],
                                            K2C, K3C, N2TOT, 2, 0);
    k_final<<<NG, 128>>>(Wl1, bl1, Wl2, bl2, (float*)d_out);
}